// round 12
// baseline (speedup 1.0000x reference)
#include <cuda_runtime.h>
#include <cuda_bf16.h>
#include <cstdint>
#include <cstddef>

#define NB 4
#define NS 2048
#define NDIM 768
#define NH 12
#define HD 64
#define NHID 3072
#define NM (NB*NS)          // 8192 rows
#define QKVLD 2304
#define SCALE 0.125f        // 64^-0.5

// ---------------- scratch (device globals: allocation-guard safe) ------------
__device__ float g_x2[(size_t)NM * NDIM];           // residual stream after attn
__device__ __nv_bfloat16 g_ahi[(size_t)NM * NDIM];  // activation hi plane
__device__ __nv_bfloat16 g_alo[(size_t)NM * NDIM];
__device__ __nv_bfloat16 g_bhi[(size_t)NM * NHID];  // mlp hidden hi plane
__device__ __nv_bfloat16 g_blo[(size_t)NM * NHID];
// head-major qkv planes: [(b*NH+h)*NS + s]*64 + d
__device__ __nv_bfloat16 g_qhi[(size_t)NM * NDIM], g_qlo[(size_t)NM * NDIM];
__device__ __nv_bfloat16 g_khi[(size_t)NM * NDIM], g_klo[(size_t)NM * NDIM];
__device__ __nv_bfloat16 g_vhi[(size_t)NM * NDIM], g_vlo[(size_t)NM * NDIM];
__device__ uint32_t g_mbits[(size_t)NB * NS * (NS / 32)];
__device__ __nv_bfloat16 g_wqkv_hi[NDIM * QKVLD], g_wqkv_lo[NDIM * QKVLD];
__device__ __nv_bfloat16 g_wproj_hi[NDIM * NDIM],  g_wproj_lo[NDIM * NDIM];
__device__ __nv_bfloat16 g_w1_hi[NDIM * NHID],     g_w1_lo[NDIM * NHID];
__device__ __nv_bfloat16 g_w2_hi[NHID * NDIM],     g_w2_lo[NHID * NDIM];

// ---------------- PTX helpers -------------------------------------------------
__device__ __forceinline__ uint32_t smem_u32(const void* p) {
    uint32_t a;
    asm("{ .reg .u64 t; cvta.to.shared.u64 t, %1; cvt.u32.u64 %0, t; }" : "=r"(a) : "l"(p));
    return a;
}
__device__ __forceinline__ void cp16(uint32_t dst, const void* src) {
    asm volatile("cp.async.cg.shared.global [%0], [%1], 16;" :: "r"(dst), "l"(src) : "memory");
}
#define CP_COMMIT() asm volatile("cp.async.commit_group;" ::: "memory")
template <int N> __device__ __forceinline__ void cp_wait() {
    asm volatile("cp.async.wait_group %0;" :: "n"(N) : "memory");
}
__device__ __forceinline__ void ldm_x4(uint32_t* r, uint32_t addr) {
    asm volatile("ldmatrix.sync.aligned.m8n8.x4.shared.b16 {%0,%1,%2,%3}, [%4];"
        : "=r"(r[0]), "=r"(r[1]), "=r"(r[2]), "=r"(r[3]) : "r"(addr));
}
__device__ __forceinline__ void ldm_x4t(uint32_t* r, uint32_t addr) {
    asm volatile("ldmatrix.sync.aligned.m8n8.x4.trans.shared.b16 {%0,%1,%2,%3}, [%4];"
        : "=r"(r[0]), "=r"(r[1]), "=r"(r[2]), "=r"(r[3]) : "r"(addr));
}
__device__ __forceinline__ void mma16816(float* c, const uint32_t* a, const uint32_t* b) {
    asm volatile("mma.sync.aligned.m16n8k16.row.col.f32.bf16.bf16.f32 "
        "{%0,%1,%2,%3}, {%4,%5,%6,%7}, {%8,%9}, {%0,%1,%2,%3};"
        : "+f"(c[0]), "+f"(c[1]), "+f"(c[2]), "+f"(c[3])
        : "r"(a[0]), "r"(a[1]), "r"(a[2]), "r"(a[3]), "r"(b[0]), "r"(b[1]));
}

// ---------------- fp32 -> (hi,lo) bf16 split ---------------------------------
__device__ __forceinline__ void split2(float v, __nv_bfloat16& h, __nv_bfloat16& l) {
    h = __float2bfloat16(v);
    l = __float2bfloat16(v - __bfloat162float(h));
}
__device__ __forceinline__ uint32_t packbf(__nv_bfloat16 a, __nv_bfloat16 b) {
    return (uint32_t)__bfloat16_as_ushort(a) | ((uint32_t)__bfloat16_as_ushort(b) << 16);
}

__global__ __launch_bounds__(256)
void split_kernel(const float* __restrict__ s, __nv_bfloat16* __restrict__ hi,
                  __nv_bfloat16* __restrict__ lo, int n4) {
    int i = blockIdx.x * 256 + threadIdx.x;
    if (i >= n4) return;
    float4 v = ((const float4*)s)[i];
    __nv_bfloat16 h0, h1, h2, h3, l0, l1, l2, l3;
    split2(v.x, h0, l0); split2(v.y, h1, l1); split2(v.z, h2, l2); split2(v.w, h3, l3);
    ((uint2*)hi)[i] = make_uint2(packbf(h0, h1), packbf(h2, h3));
    ((uint2*)lo)[i] = make_uint2(packbf(l0, l1), packbf(l2, l3));
}

// ---------------- mask -> bitmask --------------------------------------------
__global__ __launch_bounds__(256)
void pack_mask_kernel(const int* __restrict__ mask, uint32_t* __restrict__ bits) {
    int w = blockIdx.x * 256 + threadIdx.x;   // total NB*NS*64 words
    const int4* src = (const int4*)(mask + (size_t)w * 32);
    uint32_t v = 0;
#pragma unroll
    for (int c = 0; c < 8; c++) {
        int4 m = src[c];
        if (m.x) v |= 1u << (c * 4 + 0);
        if (m.y) v |= 1u << (c * 4 + 1);
        if (m.z) v |= 1u << (c * 4 + 2);
        if (m.w) v |= 1u << (c * 4 + 3);
    }
    bits[w] = v;
}

// ---------------- LayerNorm -> split bf16 planes -----------------------------
__global__ __launch_bounds__(256)
void ln_split_kernel(const float* __restrict__ x, const float* __restrict__ g,
                     const float* __restrict__ be,
                     __nv_bfloat16* __restrict__ hi, __nv_bfloat16* __restrict__ lo) {
    int row = blockIdx.x;
    const float* xr = x + (size_t)row * NDIM;
    int tid = threadIdx.x;
    float v0 = xr[tid], v1 = xr[tid + 256], v2 = xr[tid + 512];
    float s  = v0 + v1 + v2;
    float s2 = v0 * v0 + v1 * v1 + v2 * v2;
#pragma unroll
    for (int o = 16; o; o >>= 1) {
        s  += __shfl_xor_sync(0xffffffffu, s,  o);
        s2 += __shfl_xor_sync(0xffffffffu, s2, o);
    }
    __shared__ float rs[8], rs2[8];
    int w = tid >> 5, ln = tid & 31;
    if (ln == 0) { rs[w] = s; rs2[w] = s2; }
    __syncthreads();
    if (w == 0) {
        s  = (ln < 8) ? rs[ln]  : 0.f;
        s2 = (ln < 8) ? rs2[ln] : 0.f;
#pragma unroll
        for (int o = 4; o; o >>= 1) {
            s  += __shfl_xor_sync(0xffffffffu, s,  o);
            s2 += __shfl_xor_sync(0xffffffffu, s2, o);
        }
        if (ln == 0) { rs[0] = s; rs2[0] = s2; }
    }
    __syncthreads();
    float mu  = rs[0] * (1.0f / NDIM);
    float var = rs2[0] * (1.0f / NDIM) - mu * mu;
    float inv = rsqrtf(var + 1e-6f);
    size_t ro = (size_t)row * NDIM;
#pragma unroll
    for (int t = 0; t < 3; t++) {
        int c = tid + t * 256;
        float v = (t == 0 ? v0 : (t == 1 ? v1 : v2));
        float y = (v - mu) * inv * g[c] + be[c];
        __nv_bfloat16 h, l;
        split2(y, h, l);
        hi[ro + c] = h;
        lo[ro + c] = l;
    }
}

// ---------------- HMMA split-bf16 GEMM ---------------------------------------
// EPI: 0=+bias->fp32 ; 1=+bias+res->fp32 ; 2=+bias,gelu->planes ;
//      3=+bias -> head-major qkv (hi,lo) planes
#define BK 32
#define A_ROWB 80
#define B_ROWB 272
#define A_PLANE (128 * A_ROWB)
#define B_PLANE (BK * B_ROWB)
#define OFF_BHI (2 * A_PLANE)
#define OFF_BLO (OFF_BHI + B_PLANE)
#define STAGE_BYTES (OFF_BLO + B_PLANE)
#define GEMM_SMEM (3 * STAGE_BYTES)

__device__ __forceinline__ void load_stage(
    uint32_t s, const __nv_bfloat16* __restrict__ Ahi, const __nv_bfloat16* __restrict__ Alo,
    const __nv_bfloat16* __restrict__ Bhi, const __nv_bfloat16* __restrict__ Blo,
    int lda, int ldb, size_t mbase, int nbase, int k0, int tid)
{
#pragma unroll
    for (int t = 0; t < 2; t++) {
        int idx = tid + t * 256;
        int row = idx >> 2, cc = idx & 3;
        uint32_t so = s + row * A_ROWB + cc * 16;
        size_t go = (mbase + row) * (size_t)lda + k0 + cc * 8;
        cp16(so,           Ahi + go);
        cp16(so + A_PLANE, Alo + go);
    }
#pragma unroll
    for (int t = 0; t < 2; t++) {
        int idx = tid + t * 256;
        int row = idx >> 4, cc = idx & 15;
        uint32_t so = s + OFF_BHI + row * B_ROWB + cc * 16;
        size_t go = (size_t)(k0 + row) * ldb + nbase + cc * 8;
        cp16(so,           Bhi + go);
        cp16(so + B_PLANE, Blo + go);
    }
}

template <int EPI>
__global__ __launch_bounds__(256, 1)
void hmma_gemm(const __nv_bfloat16* __restrict__ Ahi, const __nv_bfloat16* __restrict__ Alo,
               const __nv_bfloat16* __restrict__ Bhi, const __nv_bfloat16* __restrict__ Blo,
               const float* __restrict__ bias, const float* __restrict__ res,
               float* __restrict__ C, __nv_bfloat16* __restrict__ Chi,
               __nv_bfloat16* __restrict__ Clo,
               __nv_bfloat16* __restrict__ Dhi, __nv_bfloat16* __restrict__ Dlo,
               __nv_bfloat16* __restrict__ Ehi, __nv_bfloat16* __restrict__ Elo,
               int N, int K)
{
    extern __shared__ char smem[];
    const uint32_t sbase = smem_u32(smem);
    const int tid = threadIdx.x;
    const int lane = tid & 31, wid = tid >> 5;
    const int wm = (wid & 1) * 64;
    const int wn = (wid >> 1) * 32;
    const size_t mbase = (size_t)blockIdx.y * 128;
    const int nbase = blockIdx.x * 128;
    const int lda = K, ldb = N;

    float acc[4][4][4];
#pragma unroll
    for (int mi = 0; mi < 4; mi++)
#pragma unroll
        for (int ni = 0; ni < 4; ni++)
#pragma unroll
            for (int q = 0; q < 4; q++) acc[mi][ni][q] = 0.f;

    const int a_row = wm + ((lane >> 3) & 1) * 8 + (lane & 7);
    const int a_k   = ((lane >> 4) & 1) * 8;
    // x4.trans B addressing: matrix idx = lane>>3 -> (kb, nb)
    const int b_krow = lane & 7;
    const int b_kb   = (lane >> 3) & 1;
    const int b_nb   = (lane >> 4) & 1;

    const int NC = K / BK;
    load_stage(sbase,               Ahi, Alo, Bhi, Blo, lda, ldb, mbase, nbase, 0,  tid); CP_COMMIT();
    load_stage(sbase + STAGE_BYTES, Ahi, Alo, Bhi, Blo, lda, ldb, mbase, nbase, BK, tid); CP_COMMIT();

    for (int i = 0; i < NC; i++) {
        if (i + 1 < NC) cp_wait<1>(); else cp_wait<0>();
        __syncthreads();
        if (i + 2 < NC) {
            load_stage(sbase + ((i + 2) % 3) * STAGE_BYTES, Ahi, Alo, Bhi, Blo,
                       lda, ldb, mbase, nbase, (i + 2) * BK, tid);
            CP_COMMIT();
        }
        const uint32_t st = sbase + (i % 3) * STAGE_BYTES;
#pragma unroll
        for (int ks = 0; ks < 2; ks++) {
            uint32_t Ah[4][4], Al[4][4];
#pragma unroll
            for (int mi = 0; mi < 4; mi++) {
                uint32_t off = (uint32_t)((a_row + mi * 16) * A_ROWB + (a_k + ks * 16) * 2);
                ldm_x4(Ah[mi], st + off);
                ldm_x4(Al[mi], st + A_PLANE + off);
            }
#pragma unroll
            for (int np = 0; np < 2; np++) {
                uint32_t Bh4[4], Bl4[4];
                uint32_t off = (uint32_t)((ks * 16 + b_kb * 8 + b_krow) * B_ROWB
                                          + (wn + np * 16 + b_nb * 8) * 2);
                ldm_x4t(Bh4, st + OFF_BHI + off);
                ldm_x4t(Bl4, st + OFF_BLO + off);
#pragma unroll
                for (int mi = 0; mi < 4; mi++) {
                    mma16816(acc[mi][2 * np],     Ah[mi], Bh4);
                    mma16816(acc[mi][2 * np],     Ah[mi], Bl4);
                    mma16816(acc[mi][2 * np],     Al[mi], Bh4);
                    mma16816(acc[mi][2 * np + 1], Ah[mi], Bh4 + 2);
                    mma16816(acc[mi][2 * np + 1], Ah[mi], Bl4 + 2);
                    mma16816(acc[mi][2 * np + 1], Al[mi], Bh4 + 2);
                }
            }
        }
    }

    const int gid = lane >> 2, q4 = lane & 3;
#pragma unroll
    for (int mi = 0; mi < 4; mi++) {
        size_t r0 = mbase + wm + mi * 16 + gid;
#pragma unroll
        for (int half = 0; half < 2; half++) {
            size_t r = r0 + half * 8;
#pragma unroll
            for (int ni = 0; ni < 4; ni++) {
                int c = nbase + wn + ni * 8 + q4 * 2;
                float v0 = acc[mi][ni][half * 2 + 0] + bias[c];
                float v1 = acc[mi][ni][half * 2 + 1] + bias[c + 1];
                if (EPI == 0) {
                    float2 v; v.x = v0; v.y = v1;
                    *(float2*)(C + r * (size_t)N + c) = v;
                } else if (EPI == 1) {
                    const float2 rr = *(const float2*)(res + r * (size_t)N + c);
                    float2 v; v.x = v0 + rr.x; v.y = v1 + rr.y;
                    *(float2*)(C + r * (size_t)N + c) = v;
                } else if (EPI == 2) {
                    v0 = 0.5f * v0 * (1.0f + erff(v0 * 0.70710678118654752f));
                    v1 = 0.5f * v1 * (1.0f + erff(v1 * 0.70710678118654752f));
                    __nv_bfloat16 h0, h1, l0, l1;
                    split2(v0, h0, l0); split2(v1, h1, l1);
                    *(uint32_t*)(Chi + r * (size_t)N + c) = packbf(h0, h1);
                    *(uint32_t*)(Clo + r * (size_t)N + c) = packbf(l0, l1);
                } else {
                    // EPI 3: head-major qkv planes
                    int which = c / NDIM;
                    int rem = c - which * NDIM;
                    int head = rem >> 6, d = rem & 63;
                    size_t dst = (((r >> 11) * NH + head) * (size_t)NS + (r & 2047)) * HD + d;
                    __nv_bfloat16 h0, h1, l0, l1;
                    split2(v0, h0, l0); split2(v1, h1, l1);
                    __nv_bfloat16* ph = (which == 0) ? Chi : (which == 1) ? Dhi : Ehi;
                    __nv_bfloat16* pl = (which == 0) ? Clo : (which == 1) ? Dlo : Elo;
                    *(uint32_t*)(ph + dst) = packbf(h0, h1);
                    *(uint32_t*)(pl + dst) = packbf(l0, l1);
                }
            }
        }
    }
}

// ---------------- HMMA flash attention ---------------------------------------
// grid (NS/128, NH, NB), 256 threads = 8 warps x 16 q-rows.
// K/V chunks of 64 keys, 3-stage cp.async pipeline; split-bf16 QK and PV.
#define AT_ROWB 144
#define AT_QPLANE (128 * AT_ROWB)            // 18432
#define AT_KV (64 * AT_ROWB)                 // 9216
#define AT_BUF (4 * AT_KV)                   // 36864
#define AT_BUF0 (2 * AT_QPLANE)              // 36864
#define ATTN_SMEM (2 * AT_QPLANE + 3 * AT_BUF)  // 147456

__device__ __forceinline__ void attn_load_kv(
    uint32_t buf, const __nv_bfloat16* __restrict__ khi, const __nv_bfloat16* __restrict__ klo,
    const __nv_bfloat16* __restrict__ vhi, const __nv_bfloat16* __restrict__ vlo,
    size_t hb, int k0, int tid)
{
#pragma unroll
    for (int t = 0; t < 2; t++) {
        int idx = tid + t * 256;
        int row = idx >> 3, cc = idx & 7;
        uint32_t so = buf + row * AT_ROWB + cc * 16;
        size_t go = hb + (size_t)(k0 + row) * HD + cc * 8;
        cp16(so,              khi + go);
        cp16(so + AT_KV,      klo + go);
        cp16(so + 2 * AT_KV,  vhi + go);
        cp16(so + 3 * AT_KV,  vlo + go);
    }
}

__global__ __launch_bounds__(256, 1)
void attn_hmma(const __nv_bfloat16* __restrict__ qhi, const __nv_bfloat16* __restrict__ qlo,
               const __nv_bfloat16* __restrict__ khi, const __nv_bfloat16* __restrict__ klo,
               const __nv_bfloat16* __restrict__ vhi, const __nv_bfloat16* __restrict__ vlo,
               const uint32_t* __restrict__ mbits,
               __nv_bfloat16* __restrict__ ohi, __nv_bfloat16* __restrict__ olo)
{
    extern __shared__ char smem[];
    const uint32_t sbase = smem_u32(smem);
    const int tid = threadIdx.x;
    const int lane = tid & 31, wid = tid >> 5;
    const int gid = lane >> 2, q4 = lane & 3;
    const int q0 = blockIdx.x * 128;
    const int h  = blockIdx.y;
    const int b  = blockIdx.z;
    const size_t hb = ((size_t)b * NH + h) * NS * HD;

    // stage Q tile (128 rows x 64 d, hi+lo)
#pragma unroll
    for (int t = 0; t < 4; t++) {
        int idx = tid + t * 256;
        int row = idx >> 3, cc = idx & 7;
        uint32_t so = sbase + row * AT_ROWB + cc * 16;
        size_t go = hb + (size_t)(q0 + row) * HD + cc * 8;
        cp16(so,             qhi + go);
        cp16(so + AT_QPLANE, qlo + go);
    }
    CP_COMMIT();
    attn_load_kv(sbase + AT_BUF0,          khi, klo, vhi, vlo, hb, 0,  tid); CP_COMMIT();
    attn_load_kv(sbase + AT_BUF0 + AT_BUF, khi, klo, vhi, vlo, hb, 64, tid); CP_COMMIT();
    cp_wait<2>();  // Q ready
    __syncthreads();

    // Q frags (16 rows per warp)
    uint32_t qh[4][4], ql[4][4];
    {
        const int a_row = wid * 16 + ((lane >> 3) & 1) * 8 + (lane & 7);
        const int a_k   = ((lane >> 4) & 1) * 8;
#pragma unroll
        for (int ks = 0; ks < 4; ks++) {
            uint32_t off = (uint32_t)(a_row * AT_ROWB + (a_k + ks * 16) * 2);
            ldm_x4(qh[ks], sbase + off);
            ldm_x4(ql[ks], sbase + AT_QPLANE + off);
        }
    }

    float o[8][4];
#pragma unroll
    for (int nf = 0; nf < 8; nf++)
#pragma unroll
        for (int q = 0; q < 4; q++) o[nf][q] = 0.f;
    float m0 = -1e30f, m1 = -1e30f, l0 = 0.f, l1 = 0.f;

    const int r0 = q0 + wid * 16 + gid;
    const uint32_t* mrow0 = mbits + ((size_t)b * NS + r0) * 64;
    const uint32_t* mrow1 = mrow0 + 8 * 64;

    // x4 (non-trans) K addressing: matrix idx = lane>>3 -> d block 0..3
    const int qk_row = lane & 7;
    const int qk_db  = (lane >> 3) & 3;
    // x4.trans V addressing: matrix idx = lane>>3 -> (kb, nb)
    const int pv_krow = lane & 7;
    const int pv_kb   = (lane >> 3) & 1;
    const int pv_nb   = (lane >> 4) & 1;

    for (int it = 0; it < 32; it++) {
        if (it < 31) cp_wait<1>(); else cp_wait<0>();
        __syncthreads();
        if (it + 2 < 32) {
            attn_load_kv(sbase + AT_BUF0 + ((it + 2) % 3) * AT_BUF,
                         khi, klo, vhi, vlo, hb, (it + 2) * 64, tid);
            CP_COMMIT();
        }
        const uint32_t buf = sbase + AT_BUF0 + (it % 3) * AT_BUF;

        // ---- S = Q K^T (split) ----
        float s[8][4];
#pragma unroll
        for (int nf = 0; nf < 8; nf++)
#pragma unroll
            for (int q = 0; q < 4; q++) s[nf][q] = 0.f;
#pragma unroll
        for (int nf = 0; nf < 8; nf++) {
#pragma unroll
            for (int ks2 = 0; ks2 < 2; ks2++) {
                uint32_t bh[4], blr[4];
                uint32_t off = (uint32_t)((nf * 8 + qk_row) * AT_ROWB
                                          + (qk_db * 8 + ks2 * 32) * 2);
                ldm_x4(bh,  buf + off);
                ldm_x4(blr, buf + AT_KV + off);
                mma16816(s[nf], qh[2 * ks2],     bh);
                mma16816(s[nf], qh[2 * ks2],     blr);
                mma16816(s[nf], ql[2 * ks2],     bh);
                mma16816(s[nf], qh[2 * ks2 + 1], bh + 2);
                mma16816(s[nf], qh[2 * ks2 + 1], blr + 2);
                mma16816(s[nf], ql[2 * ks2 + 1], bh + 2);
            }
        }

        // ---- mask + scale ----
        const uint2 mw0 = *(const uint2*)(mrow0 + it * 2);
        const uint2 mw1 = *(const uint2*)(mrow1 + it * 2);
#pragma unroll
        for (int nf = 0; nf < 8; nf++) {
            const int sh = (nf & 3) * 8 + q4 * 2;
            const uint32_t w0 = (nf < 4) ? mw0.x : mw0.y;
            const uint32_t w1 = (nf < 4) ? mw1.x : mw1.y;
            s[nf][0] = ((w0 >> sh) & 1u)       ? s[nf][0] * SCALE : -10000.f;
            s[nf][1] = ((w0 >> (sh + 1)) & 1u) ? s[nf][1] * SCALE : -10000.f;
            s[nf][2] = ((w1 >> sh) & 1u)       ? s[nf][2] * SCALE : -10000.f;
            s[nf][3] = ((w1 >> (sh + 1)) & 1u) ? s[nf][3] * SCALE : -10000.f;
        }

        // ---- online softmax ----
        float rx0 = -1e30f, rx1 = -1e30f;
#pragma unroll
        for (int nf = 0; nf < 8; nf++) {
            rx0 = fmaxf(rx0, fmaxf(s[nf][0], s[nf][1]));
            rx1 = fmaxf(rx1, fmaxf(s[nf][2], s[nf][3]));
        }
        rx0 = fmaxf(rx0, __shfl_xor_sync(0xffffffffu, rx0, 1));
        rx0 = fmaxf(rx0, __shfl_xor_sync(0xffffffffu, rx0, 2));
        rx1 = fmaxf(rx1, __shfl_xor_sync(0xffffffffu, rx1, 1));
        rx1 = fmaxf(rx1, __shfl_xor_sync(0xffffffffu, rx1, 2));
        const float nm0 = fmaxf(m0, rx0), nm1 = fmaxf(m1, rx1);
        const float c0 = __expf(m0 - nm0), c1 = __expf(m1 - nm1);
        l0 *= c0; l1 *= c1;
#pragma unroll
        for (int nf = 0; nf < 8; nf++) {
            o[nf][0] *= c0; o[nf][1] *= c0;
            o[nf][2] *= c1; o[nf][3] *= c1;
        }
#pragma unroll
        for (int nf = 0; nf < 8; nf++) {
            float p0 = __expf(s[nf][0] - nm0);
            float p1 = __expf(s[nf][1] - nm0);
            float p2 = __expf(s[nf][2] - nm1);
            float p3 = __expf(s[nf][3] - nm1);
            l0 += p0 + p1; l1 += p2 + p3;
            s[nf][0] = p0; s[nf][1] = p1; s[nf][2] = p2; s[nf][3] = p3;
        }
        m0 = nm0; m1 = nm1;

        // ---- O += P V (split P in-register) ----
#pragma unroll
        for (int kk = 0; kk < 4; kk++) {
            uint32_t ah[4], al[4];
#pragma unroll
            for (int half = 0; half < 2; half++) {
                const float* sp = s[2 * kk + half];
                __nv_bfloat16 h0, h1, h2, h3, lo0, lo1, lo2, lo3;
                split2(sp[0], h0, lo0); split2(sp[1], h1, lo1);
                split2(sp[2], h2, lo2); split2(sp[3], h3, lo3);
                ah[half * 2 + 0] = packbf(h0, h1);  al[half * 2 + 0] = packbf(lo0, lo1);
                ah[half * 2 + 1] = packbf(h2, h3);  al[half * 2 + 1] = packbf(lo2, lo3);
            }
            const uint32_t krow = (uint32_t)((kk * 16 + pv_kb * 8 + pv_krow) * AT_ROWB);
#pragma unroll
            for (int np = 0; np < 4; np++) {
                uint32_t bh[4], blr[4];
                uint32_t off = krow + (uint32_t)((np * 16 + pv_nb * 8) * 2);
                ldm_x4t(bh,  buf + 2 * AT_KV + off);
                ldm_x4t(blr, buf + 3 * AT_KV + off);
                mma16816(o[2 * np],     ah, bh);
                mma16816(o[2 * np],     ah, blr);
                mma16816(o[2 * np],     al, bh);
                mma16816(o[2 * np + 1], ah, bh + 2);
                mma16816(o[2 * np + 1], ah, blr + 2);
                mma16816(o[2 * np + 1], al, bh + 2);
            }
        }
    }

    // final l reduction across the 4 lanes sharing each row
    l0 += __shfl_xor_sync(0xffffffffu, l0, 1);
    l0 += __shfl_xor_sync(0xffffffffu, l0, 2);
    l1 += __shfl_xor_sync(0xffffffffu, l1, 1);
    l1 += __shfl_xor_sync(0xffffffffu, l1, 2);
    const float i0 = 1.0f / l0, i1 = 1.0f / l1;

    const size_t t0 = (size_t)b * NS + r0;
#pragma unroll
    for (int nf = 0; nf < 8; nf++) {
        const int c = h * HD + nf * 8 + q4 * 2;
        {
            __nv_bfloat16 h0, h1, lo0, lo1;
            split2(o[nf][0] * i0, h0, lo0);
            split2(o[nf][1] * i0, h1, lo1);
            *(uint32_t*)(ohi + t0 * NDIM + c) = packbf(h0, h1);
            *(uint32_t*)(olo + t0 * NDIM + c) = packbf(lo0, lo1);
        }
        {
            __nv_bfloat16 h0, h1, lo0, lo1;
            split2(o[nf][2] * i1, h0, lo0);
            split2(o[nf][3] * i1, h1, lo1);
            *(uint32_t*)(ohi + (t0 + 8) * NDIM + c) = packbf(h0, h1);
            *(uint32_t*)(olo + (t0 + 8) * NDIM + c) = packbf(lo0, lo1);
        }
    }
}

// ---------------- launch ------------------------------------------------------
extern "C" void kernel_launch(void* const* d_in, const int* in_sizes, int n_in,
                              void* d_out, int out_size) {
    const float* x      = (const float*)d_in[0];
    const int*   mask   = (const int*)  d_in[1];
    const float* w_qkv  = (const float*)d_in[2];
    const float* b_qkv  = (const float*)d_in[3];
    const float* w_proj = (const float*)d_in[4];
    const float* b_proj = (const float*)d_in[5];
    const float* g1     = (const float*)d_in[6];
    const float* be1    = (const float*)d_in[7];
    const float* g2     = (const float*)d_in[8];
    const float* be2    = (const float*)d_in[9];
    const float* w1     = (const float*)d_in[10];
    const float* b1     = (const float*)d_in[11];
    const float* w2     = (const float*)d_in[12];
    const float* b2     = (const float*)d_in[13];
    float* out = (float*)d_out;

    float *x2_p;
    __nv_bfloat16 *ahi, *alo, *bhi, *blo;
    __nv_bfloat16 *qh, *ql, *kh, *kl, *vh, *vl;
    uint32_t* mb;
    __nv_bfloat16 *wqh, *wql, *wph, *wpl, *w1h, *w1l, *w2h, *w2l;
    cudaGetSymbolAddress((void**)&x2_p,  g_x2);
    cudaGetSymbolAddress((void**)&ahi,   g_ahi);
    cudaGetSymbolAddress((void**)&alo,   g_alo);
    cudaGetSymbolAddress((void**)&bhi,   g_bhi);
    cudaGetSymbolAddress((void**)&blo,   g_blo);
    cudaGetSymbolAddress((void**)&qh,    g_qhi);
    cudaGetSymbolAddress((void**)&ql,    g_qlo);
    cudaGetSymbolAddress((void**)&kh,    g_khi);
    cudaGetSymbolAddress((void**)&kl,    g_klo);
    cudaGetSymbolAddress((void**)&vh,    g_vhi);
    cudaGetSymbolAddress((void**)&vl,    g_vlo);
    cudaGetSymbolAddress((void**)&mb,    g_mbits);
    cudaGetSymbolAddress((void**)&wqh,   g_wqkv_hi);
    cudaGetSymbolAddress((void**)&wql,   g_wqkv_lo);
    cudaGetSymbolAddress((void**)&wph,   g_wproj_hi);
    cudaGetSymbolAddress((void**)&wpl,   g_wproj_lo);
    cudaGetSymbolAddress((void**)&w1h,   g_w1_hi);
    cudaGetSymbolAddress((void**)&w1l,   g_w1_lo);
    cudaGetSymbolAddress((void**)&w2h,   g_w2_hi);
    cudaGetSymbolAddress((void**)&w2l,   g_w2_lo);

    cudaFuncSetAttribute(hmma_gemm<0>, cudaFuncAttributeMaxDynamicSharedMemorySize, GEMM_SMEM);
    cudaFuncSetAttribute(hmma_gemm<1>, cudaFuncAttributeMaxDynamicSharedMemorySize, GEMM_SMEM);
    cudaFuncSetAttribute(hmma_gemm<2>, cudaFuncAttributeMaxDynamicSharedMemorySize, GEMM_SMEM);
    cudaFuncSetAttribute(hmma_gemm<3>, cudaFuncAttributeMaxDynamicSharedMemorySize, GEMM_SMEM);
    cudaFuncSetAttribute(attn_hmma,    cudaFuncAttributeMaxDynamicSharedMemorySize, ATTN_SMEM);

    // weight splits + mask pack
    {
        int n4;
        n4 = NDIM * QKVLD / 4; split_kernel<<<(n4 + 255) / 256, 256>>>(w_qkv,  wqh, wql, n4);
        n4 = NDIM * NDIM / 4;  split_kernel<<<(n4 + 255) / 256, 256>>>(w_proj, wph, wpl, n4);
        n4 = NDIM * NHID / 4;  split_kernel<<<(n4 + 255) / 256, 256>>>(w1,     w1h, w1l, n4);
        n4 = NHID * NDIM / 4;  split_kernel<<<(n4 + 255) / 256, 256>>>(w2,     w2h, w2l, n4);
        pack_mask_kernel<<<(NB * NS * 64) / 256, 256>>>(mask, mb);
    }

    // 1) LN1 -> split planes
    ln_split_kernel<<<NM, 256>>>(x, g1, be1, ahi, alo);
    // 2) qkv GEMM -> head-major split planes
    hmma_gemm<3><<<dim3(QKVLD / 128, NM / 128), 256, GEMM_SMEM>>>(
        ahi, alo, wqh, wql, b_qkv, nullptr, nullptr, qh, ql, kh, kl, vh, vl, QKVLD, NDIM);
    // 3) attention -> split planes
    attn_hmma<<<dim3(NS / 128, NH, NB), 256, ATTN_SMEM>>>(
        qh, ql, kh, kl, vh, vl, mb, ahi, alo);
    // 4) x2 = x + attn @ w_proj + b_proj
    hmma_gemm<1><<<dim3(NDIM / 128, NM / 128), 256, GEMM_SMEM>>>(
        ahi, alo, wph, wpl, b_proj, x, x2_p, nullptr, nullptr,
        nullptr, nullptr, nullptr, nullptr, NDIM, NDIM);
    // 5) LN2 -> split planes
    ln_split_kernel<<<NM, 256>>>(x2_p, g2, be2, ahi, alo);
    // 6) hid = gelu(h @ w1 + b1) -> split planes
    hmma_gemm<2><<<dim3(NHID / 128, NM / 128), 256, GEMM_SMEM>>>(
        ahi, alo, w1h, w1l, b1, nullptr, nullptr, bhi, blo,
        nullptr, nullptr, nullptr, nullptr, NHID, NDIM);
    // 7) out = x2 + hid @ w2 + b2
    hmma_gemm<1><<<dim3(NDIM / 128, NM / 128), 256, GEMM_SMEM>>>(
        bhi, blo, w2h, w2l, b2, x2_p, out, nullptr, nullptr,
        nullptr, nullptr, nullptr, nullptr, NDIM, NHID);
}

// round 13
// speedup vs baseline: 1.1710x; 1.1710x over previous
#include <cuda_runtime.h>
#include <cuda_bf16.h>
#include <cstdint>
#include <cstddef>

#define NB 4
#define NS 2048
#define NDIM 768
#define NH 12
#define HD 64
#define NHID 3072
#define NM (NB*NS)          // 8192 rows
#define QKVLD 2304
#define SCALE 0.125f        // 64^-0.5

// ---------------- scratch (device globals: allocation-guard safe) ------------
__device__ float g_x2[(size_t)NM * NDIM];           // residual stream after attn
__device__ __nv_bfloat16 g_ahi[(size_t)NM * NDIM];  // activation hi plane
__device__ __nv_bfloat16 g_alo[(size_t)NM * NDIM];
__device__ __nv_bfloat16 g_bhi[(size_t)NM * NHID];  // mlp hidden hi plane
__device__ __nv_bfloat16 g_blo[(size_t)NM * NHID];
// head-major qkv planes: [(b*NH+h)*NS + s]*64 + d
__device__ __nv_bfloat16 g_qhi[(size_t)NM * NDIM], g_qlo[(size_t)NM * NDIM];
__device__ __nv_bfloat16 g_khi[(size_t)NM * NDIM], g_klo[(size_t)NM * NDIM];
__device__ __nv_bfloat16 g_vhi[(size_t)NM * NDIM], g_vlo[(size_t)NM * NDIM];
__device__ uint32_t g_mbits[(size_t)NB * NS * (NS / 32)];
__device__ __nv_bfloat16 g_wqkv_hi[NDIM * QKVLD], g_wqkv_lo[NDIM * QKVLD];
__device__ __nv_bfloat16 g_wproj_hi[NDIM * NDIM],  g_wproj_lo[NDIM * NDIM];
__device__ __nv_bfloat16 g_w1_hi[NDIM * NHID],     g_w1_lo[NDIM * NHID];
__device__ __nv_bfloat16 g_w2_hi[NHID * NDIM],     g_w2_lo[NHID * NDIM];

// ---------------- PTX helpers -------------------------------------------------
__device__ __forceinline__ uint32_t smem_u32(const void* p) {
    uint32_t a;
    asm("{ .reg .u64 t; cvta.to.shared.u64 t, %1; cvt.u32.u64 %0, t; }" : "=r"(a) : "l"(p));
    return a;
}
__device__ __forceinline__ void cp16(uint32_t dst, const void* src) {
    asm volatile("cp.async.cg.shared.global [%0], [%1], 16;" :: "r"(dst), "l"(src) : "memory");
}
#define CP_COMMIT() asm volatile("cp.async.commit_group;" ::: "memory")
template <int N> __device__ __forceinline__ void cp_wait() {
    asm volatile("cp.async.wait_group %0;" :: "n"(N) : "memory");
}
__device__ __forceinline__ void ldm_x4(uint32_t* r, uint32_t addr) {
    asm volatile("ldmatrix.sync.aligned.m8n8.x4.shared.b16 {%0,%1,%2,%3}, [%4];"
        : "=r"(r[0]), "=r"(r[1]), "=r"(r[2]), "=r"(r[3]) : "r"(addr));
}
__device__ __forceinline__ void ldm_x4t(uint32_t* r, uint32_t addr) {
    asm volatile("ldmatrix.sync.aligned.m8n8.x4.trans.shared.b16 {%0,%1,%2,%3}, [%4];"
        : "=r"(r[0]), "=r"(r[1]), "=r"(r[2]), "=r"(r[3]) : "r"(addr));
}
__device__ __forceinline__ void mma16816(float* c, const uint32_t* a, const uint32_t* b) {
    asm volatile("mma.sync.aligned.m16n8k16.row.col.f32.bf16.bf16.f32 "
        "{%0,%1,%2,%3}, {%4,%5,%6,%7}, {%8,%9}, {%0,%1,%2,%3};"
        : "+f"(c[0]), "+f"(c[1]), "+f"(c[2]), "+f"(c[3])
        : "r"(a[0]), "r"(a[1]), "r"(a[2]), "r"(a[3]), "r"(b[0]), "r"(b[1]));
}

// ---------------- fp32 -> (hi,lo) bf16 split ---------------------------------
__device__ __forceinline__ void split2(float v, __nv_bfloat16& h, __nv_bfloat16& l) {
    h = __float2bfloat16(v);
    l = __float2bfloat16(v - __bfloat162float(h));
}
__device__ __forceinline__ uint32_t packbf(__nv_bfloat16 a, __nv_bfloat16 b) {
    return (uint32_t)__bfloat16_as_ushort(a) | ((uint32_t)__bfloat16_as_ushort(b) << 16);
}

__global__ __launch_bounds__(256)
void split_kernel(const float* __restrict__ s, __nv_bfloat16* __restrict__ hi,
                  __nv_bfloat16* __restrict__ lo, int n4) {
    int i = blockIdx.x * 256 + threadIdx.x;
    if (i >= n4) return;
    float4 v = ((const float4*)s)[i];
    __nv_bfloat16 h0, h1, h2, h3, l0, l1, l2, l3;
    split2(v.x, h0, l0); split2(v.y, h1, l1); split2(v.z, h2, l2); split2(v.w, h3, l3);
    ((uint2*)hi)[i] = make_uint2(packbf(h0, h1), packbf(h2, h3));
    ((uint2*)lo)[i] = make_uint2(packbf(l0, l1), packbf(l2, l3));
}

// ---------------- mask -> bitmask --------------------------------------------
__global__ __launch_bounds__(256)
void pack_mask_kernel(const int* __restrict__ mask, uint32_t* __restrict__ bits) {
    int w = blockIdx.x * 256 + threadIdx.x;   // total NB*NS*64 words
    const int4* src = (const int4*)(mask + (size_t)w * 32);
    uint32_t v = 0;
#pragma unroll
    for (int c = 0; c < 8; c++) {
        int4 m = src[c];
        if (m.x) v |= 1u << (c * 4 + 0);
        if (m.y) v |= 1u << (c * 4 + 1);
        if (m.z) v |= 1u << (c * 4 + 2);
        if (m.w) v |= 1u << (c * 4 + 3);
    }
    bits[w] = v;
}

// ---------------- LayerNorm -> split bf16 planes -----------------------------
__global__ __launch_bounds__(256)
void ln_split_kernel(const float* __restrict__ x, const float* __restrict__ g,
                     const float* __restrict__ be,
                     __nv_bfloat16* __restrict__ hi, __nv_bfloat16* __restrict__ lo) {
    int row = blockIdx.x;
    const float* xr = x + (size_t)row * NDIM;
    int tid = threadIdx.x;
    float v0 = xr[tid], v1 = xr[tid + 256], v2 = xr[tid + 512];
    float s  = v0 + v1 + v2;
    float s2 = v0 * v0 + v1 * v1 + v2 * v2;
#pragma unroll
    for (int o = 16; o; o >>= 1) {
        s  += __shfl_xor_sync(0xffffffffu, s,  o);
        s2 += __shfl_xor_sync(0xffffffffu, s2, o);
    }
    __shared__ float rs[8], rs2[8];
    int w = tid >> 5, ln = tid & 31;
    if (ln == 0) { rs[w] = s; rs2[w] = s2; }
    __syncthreads();
    if (w == 0) {
        s  = (ln < 8) ? rs[ln]  : 0.f;
        s2 = (ln < 8) ? rs2[ln] : 0.f;
#pragma unroll
        for (int o = 4; o; o >>= 1) {
            s  += __shfl_xor_sync(0xffffffffu, s,  o);
            s2 += __shfl_xor_sync(0xffffffffu, s2, o);
        }
        if (ln == 0) { rs[0] = s; rs2[0] = s2; }
    }
    __syncthreads();
    float mu  = rs[0] * (1.0f / NDIM);
    float var = rs2[0] * (1.0f / NDIM) - mu * mu;
    float inv = rsqrtf(var + 1e-6f);
    size_t ro = (size_t)row * NDIM;
#pragma unroll
    for (int t = 0; t < 3; t++) {
        int c = tid + t * 256;
        float v = (t == 0 ? v0 : (t == 1 ? v1 : v2));
        float y = (v - mu) * inv * g[c] + be[c];
        __nv_bfloat16 h, l;
        split2(y, h, l);
        hi[ro + c] = h;
        lo[ro + c] = l;
    }
}

// ---------------- HMMA split-bf16 GEMM ---------------------------------------
// EPI: 0=+bias->fp32 ; 1=+bias+res->fp32 ; 2=+bias,gelu->planes ;
//      3=+bias -> head-major qkv (hi,lo) planes
// 2-stage pipeline + 2 CTAs/SM (16 warps/SM) to cover tensor-pipe idle phases.
#define BK 32
#define A_ROWB 80
#define B_ROWB 272
#define A_PLANE (128 * A_ROWB)
#define B_PLANE (BK * B_ROWB)
#define OFF_BHI (2 * A_PLANE)
#define OFF_BLO (OFF_BHI + B_PLANE)
#define STAGE_BYTES (OFF_BHI + 2 * B_PLANE)
#define GEMM_SMEM (2 * STAGE_BYTES)             // 75776

__device__ __forceinline__ void load_stage(
    uint32_t s, const __nv_bfloat16* __restrict__ Ahi, const __nv_bfloat16* __restrict__ Alo,
    const __nv_bfloat16* __restrict__ Bhi, const __nv_bfloat16* __restrict__ Blo,
    int lda, int ldb, size_t mbase, int nbase, int k0, int tid)
{
#pragma unroll
    for (int t = 0; t < 2; t++) {
        int idx = tid + t * 256;
        int row = idx >> 2, cc = idx & 3;
        uint32_t so = s + row * A_ROWB + cc * 16;
        size_t go = (mbase + row) * (size_t)lda + k0 + cc * 8;
        cp16(so,           Ahi + go);
        cp16(so + A_PLANE, Alo + go);
    }
#pragma unroll
    for (int t = 0; t < 2; t++) {
        int idx = tid + t * 256;
        int row = idx >> 4, cc = idx & 15;
        uint32_t so = s + OFF_BHI + row * B_ROWB + cc * 16;
        size_t go = (size_t)(k0 + row) * ldb + nbase + cc * 8;
        cp16(so,           Bhi + go);
        cp16(so + B_PLANE, Blo + go);
    }
}

template <int EPI>
__global__ __launch_bounds__(256, 2)
void hmma_gemm(const __nv_bfloat16* __restrict__ Ahi, const __nv_bfloat16* __restrict__ Alo,
               const __nv_bfloat16* __restrict__ Bhi, const __nv_bfloat16* __restrict__ Blo,
               const float* __restrict__ bias, const float* __restrict__ res,
               float* __restrict__ C, __nv_bfloat16* __restrict__ Chi,
               __nv_bfloat16* __restrict__ Clo,
               __nv_bfloat16* __restrict__ Dhi, __nv_bfloat16* __restrict__ Dlo,
               __nv_bfloat16* __restrict__ Ehi, __nv_bfloat16* __restrict__ Elo,
               int N, int K)
{
    extern __shared__ char smem[];
    const uint32_t sbase = smem_u32(smem);
    const int tid = threadIdx.x;
    const int lane = tid & 31, wid = tid >> 5;
    const int wm = (wid & 1) * 64;
    const int wn = (wid >> 1) * 32;
    const size_t mbase = (size_t)blockIdx.y * 128;
    const int nbase = blockIdx.x * 128;
    const int lda = K, ldb = N;

    float acc[4][4][4];
#pragma unroll
    for (int mi = 0; mi < 4; mi++)
#pragma unroll
        for (int ni = 0; ni < 4; ni++)
#pragma unroll
            for (int q = 0; q < 4; q++) acc[mi][ni][q] = 0.f;

    const int a_row = wm + ((lane >> 3) & 1) * 8 + (lane & 7);
    const int a_k   = ((lane >> 4) & 1) * 8;
    // x4.trans B addressing: matrix idx = lane>>3 -> (kb, nb)
    const int b_krow = lane & 7;
    const int b_kb   = (lane >> 3) & 1;
    const int b_nb   = (lane >> 4) & 1;

    const int NC = K / BK;
    load_stage(sbase, Ahi, Alo, Bhi, Blo, lda, ldb, mbase, nbase, 0, tid); CP_COMMIT();

    for (int i = 0; i < NC; i++) {
        cp_wait<0>();
        __syncthreads();
        if (i + 1 < NC) {
            load_stage(sbase + ((i + 1) & 1) * STAGE_BYTES, Ahi, Alo, Bhi, Blo,
                       lda, ldb, mbase, nbase, (i + 1) * BK, tid);
            CP_COMMIT();
        }
        const uint32_t st = sbase + (i & 1) * STAGE_BYTES;
#pragma unroll
        for (int ks = 0; ks < 2; ks++) {
            uint32_t Ah[4][4], Al[4][4];
#pragma unroll
            for (int mi = 0; mi < 4; mi++) {
                uint32_t off = (uint32_t)((a_row + mi * 16) * A_ROWB + (a_k + ks * 16) * 2);
                ldm_x4(Ah[mi], st + off);
                ldm_x4(Al[mi], st + A_PLANE + off);
            }
#pragma unroll
            for (int np = 0; np < 2; np++) {
                uint32_t Bh4[4], Bl4[4];
                uint32_t off = (uint32_t)((ks * 16 + b_kb * 8 + b_krow) * B_ROWB
                                          + (wn + np * 16 + b_nb * 8) * 2);
                ldm_x4t(Bh4, st + OFF_BHI + off);
                ldm_x4t(Bl4, st + OFF_BLO + off);
#pragma unroll
                for (int mi = 0; mi < 4; mi++) {
                    mma16816(acc[mi][2 * np],     Ah[mi], Bh4);
                    mma16816(acc[mi][2 * np],     Ah[mi], Bl4);
                    mma16816(acc[mi][2 * np],     Al[mi], Bh4);
                    mma16816(acc[mi][2 * np + 1], Ah[mi], Bh4 + 2);
                    mma16816(acc[mi][2 * np + 1], Ah[mi], Bl4 + 2);
                    mma16816(acc[mi][2 * np + 1], Al[mi], Bh4 + 2);
                }
            }
        }
    }

    const int gid = lane >> 2, q4 = lane & 3;
#pragma unroll
    for (int mi = 0; mi < 4; mi++) {
        size_t r0 = mbase + wm + mi * 16 + gid;
#pragma unroll
        for (int half = 0; half < 2; half++) {
            size_t r = r0 + half * 8;
#pragma unroll
            for (int ni = 0; ni < 4; ni++) {
                int c = nbase + wn + ni * 8 + q4 * 2;
                float v0 = acc[mi][ni][half * 2 + 0] + bias[c];
                float v1 = acc[mi][ni][half * 2 + 1] + bias[c + 1];
                if (EPI == 0) {
                    float2 v; v.x = v0; v.y = v1;
                    *(float2*)(C + r * (size_t)N + c) = v;
                } else if (EPI == 1) {
                    const float2 rr = *(const float2*)(res + r * (size_t)N + c);
                    float2 v; v.x = v0 + rr.x; v.y = v1 + rr.y;
                    *(float2*)(C + r * (size_t)N + c) = v;
                } else if (EPI == 2) {
                    v0 = 0.5f * v0 * (1.0f + erff(v0 * 0.70710678118654752f));
                    v1 = 0.5f * v1 * (1.0f + erff(v1 * 0.70710678118654752f));
                    __nv_bfloat16 h0, h1, l0, l1;
                    split2(v0, h0, l0); split2(v1, h1, l1);
                    *(uint32_t*)(Chi + r * (size_t)N + c) = packbf(h0, h1);
                    *(uint32_t*)(Clo + r * (size_t)N + c) = packbf(l0, l1);
                } else {
                    // EPI 3: head-major qkv planes
                    int which = c / NDIM;
                    int rem = c - which * NDIM;
                    int head = rem >> 6, d = rem & 63;
                    size_t dst = (((r >> 11) * NH + head) * (size_t)NS + (r & 2047)) * HD + d;
                    __nv_bfloat16 h0, h1, l0, l1;
                    split2(v0, h0, l0); split2(v1, h1, l1);
                    __nv_bfloat16* ph = (which == 0) ? Chi : (which == 1) ? Dhi : Ehi;
                    __nv_bfloat16* pl = (which == 0) ? Clo : (which == 1) ? Dlo : Elo;
                    *(uint32_t*)(ph + dst) = packbf(h0, h1);
                    *(uint32_t*)(pl + dst) = packbf(l0, l1);
                }
            }
        }
    }
}

// ---------------- HMMA flash attention ---------------------------------------
// grid (NS/128, NH, NB), 256 threads = 8 warps x 16 q-rows.
// K/V chunks of 64 keys, 2-stage cp.async pipeline, 2 CTAs/SM.
#define AT_ROWB 144
#define AT_QPLANE (128 * AT_ROWB)            // 18432
#define AT_KV (64 * AT_ROWB)                 // 9216
#define AT_BUF (4 * AT_KV)                   // 36864
#define AT_BUF0 (2 * AT_QPLANE)              // 36864
#define ATTN_SMEM (2 * AT_QPLANE + 2 * AT_BUF)  // 110592

__device__ __forceinline__ void attn_load_kv(
    uint32_t buf, const __nv_bfloat16* __restrict__ khi, const __nv_bfloat16* __restrict__ klo,
    const __nv_bfloat16* __restrict__ vhi, const __nv_bfloat16* __restrict__ vlo,
    size_t hb, int k0, int tid)
{
#pragma unroll
    for (int t = 0; t < 2; t++) {
        int idx = tid + t * 256;
        int row = idx >> 3, cc = idx & 7;
        uint32_t so = buf + row * AT_ROWB + cc * 16;
        size_t go = hb + (size_t)(k0 + row) * HD + cc * 8;
        cp16(so,              khi + go);
        cp16(so + AT_KV,      klo + go);
        cp16(so + 2 * AT_KV,  vhi + go);
        cp16(so + 3 * AT_KV,  vlo + go);
    }
}

__global__ __launch_bounds__(256, 2)
void attn_hmma(const __nv_bfloat16* __restrict__ qhi, const __nv_bfloat16* __restrict__ qlo,
               const __nv_bfloat16* __restrict__ khi, const __nv_bfloat16* __restrict__ klo,
               const __nv_bfloat16* __restrict__ vhi, const __nv_bfloat16* __restrict__ vlo,
               const uint32_t* __restrict__ mbits,
               __nv_bfloat16* __restrict__ ohi, __nv_bfloat16* __restrict__ olo)
{
    extern __shared__ char smem[];
    const uint32_t sbase = smem_u32(smem);
    const int tid = threadIdx.x;
    const int lane = tid & 31, wid = tid >> 5;
    const int gid = lane >> 2, q4 = lane & 3;
    const int q0 = blockIdx.x * 128;
    const int h  = blockIdx.y;
    const int b  = blockIdx.z;
    const size_t hb = ((size_t)b * NH + h) * NS * HD;

    // stage Q tile (128 rows x 64 d, hi+lo)
#pragma unroll
    for (int t = 0; t < 4; t++) {
        int idx = tid + t * 256;
        int row = idx >> 3, cc = idx & 7;
        uint32_t so = sbase + row * AT_ROWB + cc * 16;
        size_t go = hb + (size_t)(q0 + row) * HD + cc * 8;
        cp16(so,             qhi + go);
        cp16(so + AT_QPLANE, qlo + go);
    }
    CP_COMMIT();
    attn_load_kv(sbase + AT_BUF0, khi, klo, vhi, vlo, hb, 0, tid); CP_COMMIT();
    cp_wait<0>();  // Q + kv0 ready
    __syncthreads();

    // Q frags (16 rows per warp)
    uint32_t qh[4][4], ql[4][4];
    {
        const int a_row = wid * 16 + ((lane >> 3) & 1) * 8 + (lane & 7);
        const int a_k   = ((lane >> 4) & 1) * 8;
#pragma unroll
        for (int ks = 0; ks < 4; ks++) {
            uint32_t off = (uint32_t)(a_row * AT_ROWB + (a_k + ks * 16) * 2);
            ldm_x4(qh[ks], sbase + off);
            ldm_x4(ql[ks], sbase + AT_QPLANE + off);
        }
    }

    float o[8][4];
#pragma unroll
    for (int nf = 0; nf < 8; nf++)
#pragma unroll
        for (int q = 0; q < 4; q++) o[nf][q] = 0.f;
    float m0 = -1e30f, m1 = -1e30f, l0 = 0.f, l1 = 0.f;

    const int r0 = q0 + wid * 16 + gid;
    const uint32_t* mrow0 = mbits + ((size_t)b * NS + r0) * 64;
    const uint32_t* mrow1 = mrow0 + 8 * 64;

    // x4 (non-trans) K addressing: matrix idx = lane>>3 -> d block 0..3
    const int qk_row = lane & 7;
    const int qk_db  = (lane >> 3) & 3;
    // x4.trans V addressing: matrix idx = lane>>3 -> (kb, nb)
    const int pv_krow = lane & 7;
    const int pv_kb   = (lane >> 3) & 1;
    const int pv_nb   = (lane >> 4) & 1;

    for (int it = 0; it < 32; it++) {
        if (it > 0) {
            cp_wait<0>();
            __syncthreads();
        }
        if (it + 1 < 32) {
            attn_load_kv(sbase + AT_BUF0 + ((it + 1) & 1) * AT_BUF,
                         khi, klo, vhi, vlo, hb, (it + 1) * 64, tid);
            CP_COMMIT();
        }
        const uint32_t buf = sbase + AT_BUF0 + (it & 1) * AT_BUF;

        // ---- S = Q K^T (split) ----
        float s[8][4];
#pragma unroll
        for (int nf = 0; nf < 8; nf++)
#pragma unroll
            for (int q = 0; q < 4; q++) s[nf][q] = 0.f;
#pragma unroll
        for (int nf = 0; nf < 8; nf++) {
#pragma unroll
            for (int ks2 = 0; ks2 < 2; ks2++) {
                uint32_t bh[4], blr[4];
                uint32_t off = (uint32_t)((nf * 8 + qk_row) * AT_ROWB
                                          + (qk_db * 8 + ks2 * 32) * 2);
                ldm_x4(bh,  buf + off);
                ldm_x4(blr, buf + AT_KV + off);
                mma16816(s[nf], qh[2 * ks2],     bh);
                mma16816(s[nf], qh[2 * ks2],     blr);
                mma16816(s[nf], ql[2 * ks2],     bh);
                mma16816(s[nf], qh[2 * ks2 + 1], bh + 2);
                mma16816(s[nf], qh[2 * ks2 + 1], blr + 2);
                mma16816(s[nf], ql[2 * ks2 + 1], bh + 2);
            }
        }

        // ---- mask + scale ----
        const uint2 mw0 = *(const uint2*)(mrow0 + it * 2);
        const uint2 mw1 = *(const uint2*)(mrow1 + it * 2);
#pragma unroll
        for (int nf = 0; nf < 8; nf++) {
            const int sh = (nf & 3) * 8 + q4 * 2;
            const uint32_t w0 = (nf < 4) ? mw0.x : mw0.y;
            const uint32_t w1 = (nf < 4) ? mw1.x : mw1.y;
            s[nf][0] = ((w0 >> sh) & 1u)       ? s[nf][0] * SCALE : -10000.f;
            s[nf][1] = ((w0 >> (sh + 1)) & 1u) ? s[nf][1] * SCALE : -10000.f;
            s[nf][2] = ((w1 >> sh) & 1u)       ? s[nf][2] * SCALE : -10000.f;
            s[nf][3] = ((w1 >> (sh + 1)) & 1u) ? s[nf][3] * SCALE : -10000.f;
        }

        // ---- online softmax ----
        float rx0 = -1e30f, rx1 = -1e30f;
#pragma unroll
        for (int nf = 0; nf < 8; nf++) {
            rx0 = fmaxf(rx0, fmaxf(s[nf][0], s[nf][1]));
            rx1 = fmaxf(rx1, fmaxf(s[nf][2], s[nf][3]));
        }
        rx0 = fmaxf(rx0, __shfl_xor_sync(0xffffffffu, rx0, 1));
        rx0 = fmaxf(rx0, __shfl_xor_sync(0xffffffffu, rx0, 2));
        rx1 = fmaxf(rx1, __shfl_xor_sync(0xffffffffu, rx1, 1));
        rx1 = fmaxf(rx1, __shfl_xor_sync(0xffffffffu, rx1, 2));
        const float nm0 = fmaxf(m0, rx0), nm1 = fmaxf(m1, rx1);
        const float c0 = __expf(m0 - nm0), c1 = __expf(m1 - nm1);
        l0 *= c0; l1 *= c1;
#pragma unroll
        for (int nf = 0; nf < 8; nf++) {
            o[nf][0] *= c0; o[nf][1] *= c0;
            o[nf][2] *= c1; o[nf][3] *= c1;
        }
#pragma unroll
        for (int nf = 0; nf < 8; nf++) {
            float p0 = __expf(s[nf][0] - nm0);
            float p1 = __expf(s[nf][1] - nm0);
            float p2 = __expf(s[nf][2] - nm1);
            float p3 = __expf(s[nf][3] - nm1);
            l0 += p0 + p1; l1 += p2 + p3;
            s[nf][0] = p0; s[nf][1] = p1; s[nf][2] = p2; s[nf][3] = p3;
        }
        m0 = nm0; m1 = nm1;

        // ---- O += P V (split P in-register) ----
#pragma unroll
        for (int kk = 0; kk < 4; kk++) {
            uint32_t ah[4], al[4];
#pragma unroll
            for (int half = 0; half < 2; half++) {
                const float* sp = s[2 * kk + half];
                __nv_bfloat16 h0, h1, h2, h3, lo0, lo1, lo2, lo3;
                split2(sp[0], h0, lo0); split2(sp[1], h1, lo1);
                split2(sp[2], h2, lo2); split2(sp[3], h3, lo3);
                ah[half * 2 + 0] = packbf(h0, h1);  al[half * 2 + 0] = packbf(lo0, lo1);
                ah[half * 2 + 1] = packbf(h2, h3);  al[half * 2 + 1] = packbf(lo2, lo3);
            }
            const uint32_t krow = (uint32_t)((kk * 16 + pv_kb * 8 + pv_krow) * AT_ROWB);
#pragma unroll
            for (int np = 0; np < 4; np++) {
                uint32_t bh[4], blr[4];
                uint32_t off = krow + (uint32_t)((np * 16 + pv_nb * 8) * 2);
                ldm_x4t(bh,  buf + 2 * AT_KV + off);
                ldm_x4t(blr, buf + 3 * AT_KV + off);
                mma16816(o[2 * np],     ah, bh);
                mma16816(o[2 * np],     ah, blr);
                mma16816(o[2 * np],     al, bh);
                mma16816(o[2 * np + 1], ah, bh + 2);
                mma16816(o[2 * np + 1], ah, blr + 2);
                mma16816(o[2 * np + 1], al, bh + 2);
            }
        }
    }

    // final l reduction across the 4 lanes sharing each row
    l0 += __shfl_xor_sync(0xffffffffu, l0, 1);
    l0 += __shfl_xor_sync(0xffffffffu, l0, 2);
    l1 += __shfl_xor_sync(0xffffffffu, l1, 1);
    l1 += __shfl_xor_sync(0xffffffffu, l1, 2);
    const float i0 = 1.0f / l0, i1 = 1.0f / l1;

    const size_t t0 = (size_t)b * NS + r0;
#pragma unroll
    for (int nf = 0; nf < 8; nf++) {
        const int c = h * HD + nf * 8 + q4 * 2;
        {
            __nv_bfloat16 h0, h1, lo0, lo1;
            split2(o[nf][0] * i0, h0, lo0);
            split2(o[nf][1] * i0, h1, lo1);
            *(uint32_t*)(ohi + t0 * NDIM + c) = packbf(h0, h1);
            *(uint32_t*)(olo + t0 * NDIM + c) = packbf(lo0, lo1);
        }
        {
            __nv_bfloat16 h0, h1, lo0, lo1;
            split2(o[nf][2] * i1, h0, lo0);
            split2(o[nf][3] * i1, h1, lo1);
            *(uint32_t*)(ohi + (t0 + 8) * NDIM + c) = packbf(h0, h1);
            *(uint32_t*)(olo + (t0 + 8) * NDIM + c) = packbf(lo0, lo1);
        }
    }
}

// ---------------- launch ------------------------------------------------------
extern "C" void kernel_launch(void* const* d_in, const int* in_sizes, int n_in,
                              void* d_out, int out_size) {
    const float* x      = (const float*)d_in[0];
    const int*   mask   = (const int*)  d_in[1];
    const float* w_qkv  = (const float*)d_in[2];
    const float* b_qkv  = (const float*)d_in[3];
    const float* w_proj = (const float*)d_in[4];
    const float* b_proj = (const float*)d_in[5];
    const float* g1     = (const float*)d_in[6];
    const float* be1    = (const float*)d_in[7];
    const float* g2     = (const float*)d_in[8];
    const float* be2    = (const float*)d_in[9];
    const float* w1     = (const float*)d_in[10];
    const float* b1     = (const float*)d_in[11];
    const float* w2     = (const float*)d_in[12];
    const float* b2     = (const float*)d_in[13];
    float* out = (float*)d_out;

    float *x2_p;
    __nv_bfloat16 *ahi, *alo, *bhi, *blo;
    __nv_bfloat16 *qh, *ql, *kh, *kl, *vh, *vl;
    uint32_t* mb;
    __nv_bfloat16 *wqh, *wql, *wph, *wpl, *w1h, *w1l, *w2h, *w2l;
    cudaGetSymbolAddress((void**)&x2_p,  g_x2);
    cudaGetSymbolAddress((void**)&ahi,   g_ahi);
    cudaGetSymbolAddress((void**)&alo,   g_alo);
    cudaGetSymbolAddress((void**)&bhi,   g_bhi);
    cudaGetSymbolAddress((void**)&blo,   g_blo);
    cudaGetSymbolAddress((void**)&qh,    g_qhi);
    cudaGetSymbolAddress((void**)&ql,    g_qlo);
    cudaGetSymbolAddress((void**)&kh,    g_khi);
    cudaGetSymbolAddress((void**)&kl,    g_klo);
    cudaGetSymbolAddress((void**)&vh,    g_vhi);
    cudaGetSymbolAddress((void**)&vl,    g_vlo);
    cudaGetSymbolAddress((void**)&mb,    g_mbits);
    cudaGetSymbolAddress((void**)&wqh,   g_wqkv_hi);
    cudaGetSymbolAddress((void**)&wql,   g_wqkv_lo);
    cudaGetSymbolAddress((void**)&wph,   g_wproj_hi);
    cudaGetSymbolAddress((void**)&wpl,   g_wproj_lo);
    cudaGetSymbolAddress((void**)&w1h,   g_w1_hi);
    cudaGetSymbolAddress((void**)&w1l,   g_w1_lo);
    cudaGetSymbolAddress((void**)&w2h,   g_w2_hi);
    cudaGetSymbolAddress((void**)&w2l,   g_w2_lo);

    cudaFuncSetAttribute(hmma_gemm<0>, cudaFuncAttributeMaxDynamicSharedMemorySize, GEMM_SMEM);
    cudaFuncSetAttribute(hmma_gemm<1>, cudaFuncAttributeMaxDynamicSharedMemorySize, GEMM_SMEM);
    cudaFuncSetAttribute(hmma_gemm<2>, cudaFuncAttributeMaxDynamicSharedMemorySize, GEMM_SMEM);
    cudaFuncSetAttribute(hmma_gemm<3>, cudaFuncAttributeMaxDynamicSharedMemorySize, GEMM_SMEM);
    cudaFuncSetAttribute(attn_hmma,    cudaFuncAttributeMaxDynamicSharedMemorySize, ATTN_SMEM);

    // weight splits + mask pack
    {
        int n4;
        n4 = NDIM * QKVLD / 4; split_kernel<<<(n4 + 255) / 256, 256>>>(w_qkv,  wqh, wql, n4);
        n4 = NDIM * NDIM / 4;  split_kernel<<<(n4 + 255) / 256, 256>>>(w_proj, wph, wpl, n4);
        n4 = NDIM * NHID / 4;  split_kernel<<<(n4 + 255) / 256, 256>>>(w1,     w1h, w1l, n4);
        n4 = NHID * NDIM / 4;  split_kernel<<<(n4 + 255) / 256, 256>>>(w2,     w2h, w2l, n4);
        pack_mask_kernel<<<(NB * NS * 64) / 256, 256>>>(mask, mb);
    }

    // 1) LN1 -> split planes
    ln_split_kernel<<<NM, 256>>>(x, g1, be1, ahi, alo);
    // 2) qkv GEMM -> head-major split planes
    hmma_gemm<3><<<dim3(QKVLD / 128, NM / 128), 256, GEMM_SMEM>>>(
        ahi, alo, wqh, wql, b_qkv, nullptr, nullptr, qh, ql, kh, kl, vh, vl, QKVLD, NDIM);
    // 3) attention -> split planes
    attn_hmma<<<dim3(NS / 128, NH, NB), 256, ATTN_SMEM>>>(
        qh, ql, kh, kl, vh, vl, mb, ahi, alo);
    // 4) x2 = x + attn @ w_proj + b_proj
    hmma_gemm<1><<<dim3(NDIM / 128, NM / 128), 256, GEMM_SMEM>>>(
        ahi, alo, wph, wpl, b_proj, x, x2_p, nullptr, nullptr,
        nullptr, nullptr, nullptr, nullptr, NDIM, NDIM);
    // 5) LN2 -> split planes
    ln_split_kernel<<<NM, 256>>>(x2_p, g2, be2, ahi, alo);
    // 6) hid = gelu(h @ w1 + b1) -> split planes
    hmma_gemm<2><<<dim3(NHID / 128, NM / 128), 256, GEMM_SMEM>>>(
        ahi, alo, w1h, w1l, b1, nullptr, nullptr, bhi, blo,
        nullptr, nullptr, nullptr, nullptr, NHID, NDIM);
    // 7) out = x2 + hid @ w2 + b2
    hmma_gemm<1><<<dim3(NDIM / 128, NM / 128), 256, GEMM_SMEM>>>(
        bhi, blo, w2h, w2l, b2, x2_p, out, nullptr, nullptr,
        nullptr, nullptr, nullptr, nullptr, NDIM, NHID);
}